// round 11
// baseline (speedup 1.0000x reference)
#include <cuda_runtime.h>
#include <math.h>

#define NB 16
#define NC 64
#define NH 128
#define NW 128
#define PI2 6.283185307179586f

// ---------------- scratch ------------------------------------------------
__device__ float2 d_X [NB*256*64];        // [b][kl][i]
__device__ float2 d_Y [NB*256*64];        // [b][kl][o]
__device__ float  d_Z1[NB*NH*64*32];      // [b][h][o][0..15 zr |16..31 zi] (tf32)
__device__ float2 d_Wt[256*64*64];        // [kl][i*64+o]
__device__ float  d_proj[NB*NC];
__device__ float  d_Eout [32*128];        // [n][w]: n<16 cos, n>=16 -sin (tf32)
__device__ float  d_EoutT[128*32];        // [w][n]  transposed copy
__device__ float2 d_twdp[128];            // e^{+i 2pi m/128}

// ---------------- helpers ------------------------------------------------
__device__ __forceinline__ unsigned tf32u(float f) {
    unsigned r; asm("cvt.rna.tf32.f32 %0, %1;" : "=r"(r) : "f"(f)); return r;
}
__device__ __forceinline__ float tf32f(float f) { return __uint_as_float(tf32u(f)); }
__device__ __forceinline__ void mma_tf32(float* c,
    unsigned a0, unsigned a1, unsigned a2, unsigned a3, unsigned b0, unsigned b1) {
    asm volatile(
        "mma.sync.aligned.m16n8k8.row.col.f32.tf32.tf32.f32 "
        "{%0,%1,%2,%3}, {%4,%5,%6,%7}, {%8,%9}, {%0,%1,%2,%3};"
        : "+f"(c[0]), "+f"(c[1]), "+f"(c[2]), "+f"(c[3])
        : "r"(a0), "r"(a1), "r"(a2), "r"(a3), "r"(b0), "r"(b1));
}
__device__ __forceinline__ unsigned s2u(const void* p) {
    unsigned a;
    asm("{ .reg .u64 t; cvta.to.shared.u64 t, %1; cvt.u32.u64 %0, t; }" : "=r"(a) : "l"(p));
    return a;
}
__device__ __forceinline__ void ldsm4(unsigned &r0, unsigned &r1, unsigned &r2,
                                      unsigned &r3, unsigned a) {
    asm volatile("ldmatrix.sync.aligned.m8n8.x4.shared.b16 {%0,%1,%2,%3}, [%4];"
        : "=r"(r0), "=r"(r1), "=r"(r2), "=r"(r3) : "r"(a));
}
__device__ __forceinline__ void cpa16(unsigned dst, const void* src) {
    asm volatile("cp.async.ca.shared.global [%0], [%1], 16;" :: "r"(dst), "l"(src));
}
__device__ __forceinline__ void cpa_commit() {
    asm volatile("cp.async.commit_group;");
}
__device__ __forceinline__ void cpa_wait_all() {
    asm volatile("cp.async.wait_group 0;" ::: "memory");
}
template<int N>
__device__ __forceinline__ void cpa_wait_n() {
    asm volatile("cp.async.wait_group %0;" :: "n"(N) : "memory");
}

// ---------------- precompute ---------------------------------------------
__global__ void k_prep() {
    int t = threadIdx.x;                       // 256
    for (int idx = t; idx < 4096; idx += 256) {
        int r = idx >> 7, w = idx & 127;
        int l = r & 15;
        float s, c;
        sincosf(PI2 * (float)((l*w) & 127) * (1.f/128.f), &s, &c);
        float v = tf32f(r < 16 ? c : -s);
        d_Eout[idx] = v;
        d_EoutT[w*32 + r] = v;
    }
    if (t < 128) {
        float s, c; sincosf(PI2 * t * (1.f/128.f), &s, &c);
        d_twdp[t] = make_float2(c, s);
    }
}

// ---------------- temb projection ---------------------------------------
__global__ void k_proj(const float* __restrict__ temb,
                       const float* __restrict__ twm,
                       const float* __restrict__ tbv) {
    __shared__ float s_silu[512];
    int b = blockIdx.x, cg = blockIdx.y, t = threadIdx.x;   // 256 threads
    for (int j = t; j < 512; j += 256) {
        float v = temb[b*512 + j];
        s_silu[j] = v / (1.f + __expf(-v));
    }
    __syncthreads();
    int w = t >> 5, lane = t & 31;
    int c = cg*8 + w;
    float acc = 0.f;
    #pragma unroll 4
    for (int j = lane; j < 512; j += 32) acc += s_silu[j] * twm[c*512 + j];
    #pragma unroll
    for (int off = 16; off > 0; off >>= 1)
        acc += __shfl_xor_sync(0xffffffffu, acc, off);
    if (lane == 0) d_proj[b*64 + c] = acc + tbv[c];
}

// ---------------- weight transpose: [i,o,k,l] -> [kl][i*64+o] ------------
__global__ void k_wt(const float* __restrict__ wr, const float* __restrict__ wi) {
    __shared__ float tr[32][33], ti[32][33];
    int kl0 = blockIdx.x * 32, io0 = blockIdx.y * 32;
    for (int r = threadIdx.y; r < 32; r += 8) {
        tr[r][threadIdx.x] = wr[(io0 + r)*256 + kl0 + threadIdx.x];
        ti[r][threadIdx.x] = wi[(io0 + r)*256 + kl0 + threadIdx.x];
    }
    __syncthreads();
    for (int r = threadIdx.y; r < 32; r += 8) {
        d_Wt[(kl0 + r)*4096 + io0 + threadIdx.x] =
            make_float2(tr[threadIdx.x][r], ti[threadIdx.x][r]);
    }
}

// ---------------- fused forward DFT (one block = one bi, 8 warps) --------
// Stage 1 (x4 hq, pipelined): P[n][h] = sum_w x[h,w] * E[n,w]  -> smem
//   8 warps each own an m16n8 sub-tile of the 32x32 output tile.
// Stage 2: 8 warps = 8 chains (mt: cos/-sin) x (nt: Pr/Pi x l-half)
#define FWD_SMEM ((32*132 + 2*32*132 + 32*132)*4)
__global__ __launch_bounds__(256) void k_fwd(const float* __restrict__ x) {
    extern __shared__ float sm[];
    float* Es = sm;                    // [32 n][132 w|h]
    float* xs = sm + 32*132;           // [2 stage][32 h][132 w]
    float* Pb = sm + 3*32*132;         // [32 n][132 h]
    float* Cs = xs;                    // stage-2 combine buffer [8][16][8]
    int t = threadIdx.x, lane = t & 31, warp = t >> 5;
    int bi = blockIdx.x, b = bi >> 6, ci = bi & 63;

    unsigned EsA = s2u(Es), xsA = s2u(xs), PbA = s2u(Pb);
    const float* xp = x + (size_t)bi * 16384;

    // prologue: E + x tile 0  (group 0)
    for (int idx = t; idx < 1024; idx += 256) {
        int r = idx >> 5, c4 = idx & 31;
        cpa16(EsA + (r*132 + c4*4)*4, d_Eout + r*128 + c4*4);
    }
    for (int idx = t; idx < 1024; idx += 256) {
        int hh = idx >> 5, w4 = idx & 31;
        cpa16(xsA + (hh*132 + w4*4)*4, xp + hh*128 + w4*4);
    }
    cpa_commit();

    int qr = lane >> 2, qc = lane & 3, lr = lane & 7, lg = lane >> 3;

    // ---- stage 1: 4 hq tiles, 8 warps per tile, double-buffered x ----
    {
        int m0 = (warp & 1)*16, n0 = (warp >> 1)*8;
        unsigned bBase = EsA + ((n0 + lr)*132 + (lg & 1)*4)*4;  // n8 (dup halves)
        #pragma unroll
        for (int hq = 0; hq < 4; hq++) {
            if (hq < 3) {
                unsigned dstA = xsA + ((hq+1) & 1)*4224*4;
                const float* src = xp + (hq+1)*4096;
                for (int idx = t; idx < 1024; idx += 256) {
                    int hh = idx >> 5, w4 = idx & 31;
                    cpa16(dstA + (hh*132 + w4*4)*4, src + hh*128 + w4*4);
                }
                cpa_commit();
                cpa_wait_n<1>();
            } else {
                cpa_wait_all();
            }
            __syncthreads();

            unsigned aBase = xsA + (hq & 1)*4224*4
                           + ((m0 + lr + (lg & 1)*8)*132 + (lg >> 1)*4)*4;

            float acc[4];
            acc[0] = acc[1] = acc[2] = acc[3] = 0.f;
            #pragma unroll
            for (int kk = 0; kk < 16; kk++) {
                unsigned a0, a1, a2, a3, b0, b1, b2, b3;
                ldsm4(a0, a1, a2, a3, aBase + kk*32);
                ldsm4(b0, b1, b2, b3, bBase + kk*32);
                mma_tf32(acc, a0, a1, a2, a3, b0, b1);
            }
            // C[m16 h, n8] -> P[n][h]
            #pragma unroll
            for (int half = 0; half < 2; half++)
                #pragma unroll
                for (int cc = 0; cc < 2; cc++)
                    Pb[(n0 + 2*qc + cc)*132 + hq*32 + m0 + qr + half*8] =
                        tf32f(acc[half*2 + cc]);
            __syncthreads();
        }
    }

    // ---- stage 2: 8 warps, one chain each ----
    {
        int mt = warp & 1, nt = warp >> 1;   // mt: 0=cos rows,1=-sin rows; nt: Pr/Pi x lhalf
        unsigned aB = EsA + ((mt*16 + lr + (lg & 1)*8)*132 + (lg >> 1)*4)*4;
        unsigned bB = PbA + ((nt*8 + lr)*132 + (lg & 1)*4)*4;

        float acc[4];
        acc[0] = acc[1] = acc[2] = acc[3] = 0.f;
        #pragma unroll
        for (int kk = 0; kk < 16; kk++) {
            unsigned a0, a1, a2, a3, b0, b1, b2, b3;
            ldsm4(a0, a1, a2, a3, aB + kk*32);
            ldsm4(b0, b1, b2, b3, bB + kk*32);
            mma_tf32(acc, a0, a1, a2, a3, b0, b1);
        }
        __syncthreads();   // xs no longer needed; reuse as Cs
        // Cs[(mt*4+nt)][k(16)][lm(8)]
        #pragma unroll
        for (int half = 0; half < 2; half++)
            #pragma unroll
            for (int cc = 0; cc < 2; cc++)
                Cs[((mt*4 + nt)*16 + qr + half*8)*8 + 2*qc + cc] =
                    acc[half*2 + cc];
    }
    __syncthreads();

    // combine + store: t -> (k, l)
    {
        int k = t >> 4, l = t & 15;
        int lh = l >> 3, lm = l & 7;
        float cPr = Cs[((0*4 + lh    )*16 + k)*8 + lm];
        float cPi = Cs[((0*4 + 2 + lh)*16 + k)*8 + lm];
        float sPr = Cs[((1*4 + lh    )*16 + k)*8 + lm];
        float sPi = Cs[((1*4 + 2 + lh)*16 + k)*8 + lm];
        float xr = (cPr - sPi) * (1.f/128.f);
        float xi = (cPi + sPr) * (1.f/128.f);
        d_X[((size_t)b*256 + k*16 + l)*64 + ci] = make_float2(xr, xi);
    }
}

// ---------------- per-mode channel mixing (o-split x4) -------------------
__global__ __launch_bounds__(256) void k_mix() {
    __shared__ float2 Ws[64*16];    // [i][ol]
    __shared__ float2 Xs[16*64];    // [b][i]
    int kl = blockIdx.x, oq = blockIdx.y, t = threadIdx.x;
    for (int idx = t; idx < 1024; idx += 256)
        Ws[idx] = d_Wt[kl*4096 + (idx >> 4)*64 + oq*16 + (idx & 15)];
    for (int idx = t; idx < 1024; idx += 256)
        Xs[idx] = d_X[((size_t)(idx >> 6)*256 + kl)*64 + (idx & 63)];
    __syncthreads();
    int ol = t & 15, b = t >> 4;
    float yr = 0.f, yi = 0.f;
    #pragma unroll 8
    for (int i = 0; i < 64; i++) {
        float2 xv = Xs[b*64 + i];
        float2 wv = Ws[i*16 + ol];
        yr += xv.x*wv.x - xv.y*wv.y;
        yi += xv.x*wv.y + xv.y*wv.x;
    }
    d_Y[((size_t)b*256 + kl)*64 + oq*16 + ol] = make_float2(yr, yi);
}

// ---------------- inverse stage 1 (over k) -------------------------------
__global__ __launch_bounds__(256) void k_invh() {
    __shared__ float2 Ys[256];
    __shared__ float2 twd[128];
    int t = threadIdx.x, bo = blockIdx.x;
    int b = bo >> 6, o = bo & 63;
    if (t < 128) twd[t] = d_twdp[t];
    Ys[t] = d_Y[((size_t)b*256 + t)*64 + o];
    __syncthreads();
    #pragma unroll
    for (int rep = 0; rep < 8; rep++) {
        int idx = rep*256 + t;
        int h = idx >> 4, l = idx & 15;
        float zr = 0.f, zi = 0.f;
        #pragma unroll
        for (int k = 0; k < 16; k++) {
            float2 y = Ys[k*16 + l];
            float2 e = twd[(k*h) & 127];
            zr += y.x*e.x - y.y*e.y;
            zi += y.x*e.y + y.y*e.x;
        }
        float f = (l == 0 ? 1.f : 2.f) * (1.f/128.f);
        float* zp = d_Z1 + (((size_t)b*128 + h)*64 + o)*32;
        zp[l]      = tf32f(zr*f);
        zp[16 + l] = tf32f(zi*f);
    }
}

// ---------------- fused final (w-split): C[64o,64w] = A[64,96]@B[96,64] --
#define KP 100
#define AP 100
#define OUT_SMEM ((64*KP + 64*AP + 128)*4)
__global__ __launch_bounds__(256) void k_out(const float* __restrict__ x,
                                             const float* __restrict__ bw,
                                             const float* __restrict__ bb,
                                             float* __restrict__ out) {
    extern __shared__ float sm[];
    float* Bt  = sm;               // [64 w][KP]
    float* As  = Bt + 64*KP;       // [64 o][AP]
    float* bbp = As + 64*AP;

    int t = threadIdx.x;           // 256 = 8 warps
    int b = blockIdx.x >> 7, h = blockIdx.x & 127;
    int wq = blockIdx.y;           // 0/1 -> w half

    unsigned BtA = s2u(Bt), AsA = s2u(As);

    // As cols 0..63: bw rows (raw f32, HW-truncated by mma)
    for (int idx = t; idx < 1024; idx += 256) {
        int o = idx >> 4, c4 = idx & 15;
        cpa16(AsA + (o*AP + c4*4)*4, bw + o*64 + c4*4);
    }
    // As cols 64..95: Z1 row (zr|zi, pre-rounded)
    for (int idx = t; idx < 512; idx += 256) {
        int o = idx >> 3, c4 = idx & 7;
        cpa16(AsA + (o*AP + 64 + c4*4)*4,
              d_Z1 + (((size_t)b*128 + h)*64 + o)*32 + c4*4);
    }
    // Bt cols 64..95: EoutT rows
    for (int idx = t; idx < 512; idx += 256) {
        int w = idx >> 3, c4 = idx & 7;
        cpa16(BtA + (w*KP + 64 + c4*4)*4, d_EoutT + (wq*64 + w)*32 + c4*4);
    }
    // Bt cols 0..63: x transposed (raw f32)
    for (int idx = t; idx < 1024; idx += 256) {
        int i = idx >> 4, w4 = idx & 15;
        float4 v = *(const float4*)(x + (((size_t)(b*64 + i))*128 + h)*128
                                      + wq*64 + w4*4);
        Bt[(w4*4+0)*KP + i] = v.x;
        Bt[(w4*4+1)*KP + i] = v.y;
        Bt[(w4*4+2)*KP + i] = v.z;
        Bt[(w4*4+3)*KP + i] = v.w;
    }
    if (t < 64) bbp[t] = bb[t];
    else if (t < 128) bbp[t] = d_proj[b*64 + (t - 64)];
    cpa_commit();
    cpa_wait_all();
    __syncthreads();

    int lane = t & 31, warp = t >> 5;
    int m0 = (warp & 3) * 16, n0 = (warp >> 2) * 32;
    int qr = lane >> 2, qc = lane & 3;
    int lr = lane & 7, lg = lane >> 3;

    unsigned aBase = AsA + ((m0 + lr + (lg & 1)*8)*AP + (lg >> 1)*4)*4;
    unsigned bBase = BtA + ((n0 + lr + (lg >> 1)*8)*KP + (lg & 1)*4)*4;

    float acc[4][4];
    #pragma unroll
    for (int nt = 0; nt < 4; nt++)
        #pragma unroll
        for (int j = 0; j < 4; j++) acc[nt][j] = 0.f;

    #pragma unroll
    for (int kk = 0; kk < 12; kk++) {
        unsigned a0, a1, a2, a3;
        ldsm4(a0, a1, a2, a3, aBase + kk*32);
        #pragma unroll
        for (int p = 0; p < 2; p++) {
            unsigned b0, b1, b2, b3;
            ldsm4(b0, b1, b2, b3, bBase + p*16*KP*4 + kk*32);
            mma_tf32(acc[2*p],   a0, a1, a2, a3, b0, b1);
            mma_tf32(acc[2*p+1], a0, a1, a2, a3, b2, b3);
        }
    }

    #pragma unroll
    for (int nt = 0; nt < 4; nt++) {
        #pragma unroll
        for (int half = 0; half < 2; half++) {
            int o = m0 + qr + half*8;
            float bias = bbp[o], pr = bbp[64 + o];
            float v0 = acc[nt][half*2 + 0] + bias;
            float v1 = acc[nt][half*2 + 1] + bias;
            v0 = 0.5f * v0 * (1.f + erff(v0 * 0.70710678118f)) + pr;
            v1 = 0.5f * v1 * (1.f + erff(v1 * 0.70710678118f)) + pr;
            int w = wq*64 + n0 + nt*8 + qc*2;
            *(float2*)(out + (((size_t)(b*64 + o))*128 + h)*128 + w) =
                make_float2(v0, v1);
        }
    }
}

// ---------------- launcher ----------------------------------------------
extern "C" void kernel_launch(void* const* d_in, const int* in_sizes, int n_in,
                              void* d_out, int out_size) {
    const float* x    = (const float*)d_in[0];
    const float* temb = (const float*)d_in[1];
    const float* wr   = (const float*)d_in[2];
    const float* wi   = (const float*)d_in[3];
    const float* bw   = (const float*)d_in[4];
    const float* bb   = (const float*)d_in[5];
    const float* twm  = (const float*)d_in[6];
    const float* tbv  = (const float*)d_in[7];
    float* out = (float*)d_out;

    cudaFuncSetAttribute(k_fwd, cudaFuncAttributeMaxDynamicSharedMemorySize, FWD_SMEM);
    cudaFuncSetAttribute(k_out, cudaFuncAttributeMaxDynamicSharedMemorySize, OUT_SMEM);

    k_prep<<<1, 256>>>();
    k_proj<<<dim3(NB, 8), 256>>>(temb, twm, tbv);
    k_wt  <<<dim3(8, 128), dim3(32, 8)>>>(wr, wi);
    k_fwd <<<NB*NC, 256, FWD_SMEM>>>(x);
    k_mix <<<dim3(256, 4), 256>>>();
    k_invh<<<NB*NC, 256>>>();
    k_out <<<dim3(NB*NH, 2), 256, OUT_SMEM>>>(x, bw, bb, out);
}

// round 14
// speedup vs baseline: 1.0856x; 1.0856x over previous
#include <cuda_runtime.h>
#include <math.h>

#define NB 16
#define NC 64
#define NH 128
#define NW 128
#define PI2 6.283185307179586f

// ---------------- scratch ------------------------------------------------
__device__ float2 d_X [NB*256*64];        // [b][kl][i]
__device__ float2 d_Y [NB*256*64];        // [b][kl][o]
__device__ float  d_Z1[NB*NH*64*32];      // [b][h][o][0..15 zr |16..31 zi] (tf32)
__device__ float2 d_Wt[256*64*64];        // [kl][i*64+o]
__device__ float  d_proj[NB*NC];
__device__ float  d_Eout [32*128];        // [n][w]: n<16 cos, n>=16 -sin (tf32)
__device__ float  d_EoutT[128*32];        // [w][n]  transposed copy
__device__ float2 d_twdp[128];            // e^{+i 2pi m/128}

// ---------------- helpers ------------------------------------------------
__device__ __forceinline__ unsigned tf32u(float f) {
    unsigned r; asm("cvt.rna.tf32.f32 %0, %1;" : "=r"(r) : "f"(f)); return r;
}
__device__ __forceinline__ float tf32f(float f) { return __uint_as_float(tf32u(f)); }
__device__ __forceinline__ void mma_tf32(float* c,
    unsigned a0, unsigned a1, unsigned a2, unsigned a3, unsigned b0, unsigned b1) {
    asm volatile(
        "mma.sync.aligned.m16n8k8.row.col.f32.tf32.tf32.f32 "
        "{%0,%1,%2,%3}, {%4,%5,%6,%7}, {%8,%9}, {%0,%1,%2,%3};"
        : "+f"(c[0]), "+f"(c[1]), "+f"(c[2]), "+f"(c[3])
        : "r"(a0), "r"(a1), "r"(a2), "r"(a3), "r"(b0), "r"(b1));
}
__device__ __forceinline__ unsigned s2u(const void* p) {
    unsigned a;
    asm("{ .reg .u64 t; cvta.to.shared.u64 t, %1; cvt.u32.u64 %0, t; }" : "=r"(a) : "l"(p));
    return a;
}
__device__ __forceinline__ void ldsm4(unsigned &r0, unsigned &r1, unsigned &r2,
                                      unsigned &r3, unsigned a) {
    asm volatile("ldmatrix.sync.aligned.m8n8.x4.shared.b16 {%0,%1,%2,%3}, [%4];"
        : "=r"(r0), "=r"(r1), "=r"(r2), "=r"(r3) : "r"(a));
}
__device__ __forceinline__ void ldsm2(unsigned &r0, unsigned &r1, unsigned a) {
    asm volatile("ldmatrix.sync.aligned.m8n8.x2.shared.b16 {%0,%1}, [%2];"
        : "=r"(r0), "=r"(r1) : "r"(a));
}
__device__ __forceinline__ void cpa16(unsigned dst, const void* src) {
    asm volatile("cp.async.ca.shared.global [%0], [%1], 16;" :: "r"(dst), "l"(src));
}
__device__ __forceinline__ void cpa_commit() {
    asm volatile("cp.async.commit_group;");
}
__device__ __forceinline__ void cpa_wait_all() {
    asm volatile("cp.async.wait_group 0;" ::: "memory");
}

// ---------------- merged preprocessing (prep | proj | wt) ----------------
__global__ __launch_bounds__(256) void k_pre(const float* __restrict__ temb,
                                             const float* __restrict__ twm,
                                             const float* __restrict__ tbv,
                                             const float* __restrict__ wr,
                                             const float* __restrict__ wi) {
    __shared__ float sbuf[2*32*33];
    int bid = blockIdx.x, t = threadIdx.x;

    if (bid == 0) {
        // twiddle tables
        for (int idx = t; idx < 4096; idx += 256) {
            int r = idx >> 7, w = idx & 127;
            int l = r & 15;
            float s, c;
            sincosf(PI2 * (float)((l*w) & 127) * (1.f/128.f), &s, &c);
            float v = tf32f(r < 16 ? c : -s);
            d_Eout[idx] = v;
            d_EoutT[w*32 + r] = v;
        }
        if (t < 128) {
            float s, c; sincosf(PI2 * t * (1.f/128.f), &s, &c);
            d_twdp[t] = make_float2(c, s);
        }
    } else if (bid <= 128) {
        // temb projection: b = (bid-1)>>3, cg = (bid-1)&7
        int b = (bid - 1) >> 3, cg = (bid - 1) & 7;
        float* s_silu = sbuf;
        for (int j = t; j < 512; j += 256) {
            float v = temb[b*512 + j];
            s_silu[j] = v / (1.f + __expf(-v));
        }
        __syncthreads();
        int w = t >> 5, lane = t & 31;
        int c = cg*8 + w;
        float acc = 0.f;
        #pragma unroll 4
        for (int j = lane; j < 512; j += 32) acc += s_silu[j] * twm[c*512 + j];
        #pragma unroll
        for (int off = 16; off > 0; off >>= 1)
            acc += __shfl_xor_sync(0xffffffffu, acc, off);
        if (lane == 0) d_proj[b*64 + c] = acc + tbv[c];
    } else {
        // weight transpose: q in [0,1024)
        int q = bid - 129;
        int kl0 = (q & 7) * 32, io0 = (q >> 3) * 32;
        float* tr = sbuf;              // [32][33]
        float* ti = sbuf + 32*33;      // [32][33]
        int tx = t & 31, ty = t >> 5;
        for (int r = ty; r < 32; r += 8) {
            tr[r*33 + tx] = wr[(io0 + r)*256 + kl0 + tx];
            ti[r*33 + tx] = wi[(io0 + r)*256 + kl0 + tx];
        }
        __syncthreads();
        for (int r = ty; r < 32; r += 8) {
            d_Wt[(kl0 + r)*4096 + io0 + tx] =
                make_float2(tr[tx*33 + r], ti[tx*33 + r]);
        }
    }
}

// ---------------- fused forward DFT (one block = one bi, 8 warps) --------
// Stage 1 (x4 hq): P[n][h] = sum_w x[h,w] * E[n,w]   (single x buffer)
// Stage 2: 8 warps = 8 chains (cos/-sin) x (Pr/Pi) x (l-half)
#define FWD_SMEM ((32*132 + 32*132 + 32*132)*4)
__global__ __launch_bounds__(256) void k_fwd(const float* __restrict__ x) {
    extern __shared__ float sm[];
    float* Es = sm;                    // [32 n][132 w|h]
    float* xs = sm + 32*132;           // [32 h][132 w]
    float* Pb = sm + 2*32*132;         // [32 n][132 h]
    float* Cs = xs;                    // stage-2 combine buffer [8][16][8]
    int t = threadIdx.x, lane = t & 31, warp = t >> 5;
    int bi = blockIdx.x, b = bi >> 6, ci = bi & 63;

    unsigned EsA = s2u(Es), xsA = s2u(xs), PbA = s2u(Pb);
    const float* xp = x + (size_t)bi * 16384;

    // prologue: E + x tile 0
    for (int idx = t; idx < 1024; idx += 256) {
        int r = idx >> 5, c4 = idx & 31;
        cpa16(EsA + (r*132 + c4*4)*4, d_Eout + r*128 + c4*4);
    }
    for (int idx = t; idx < 1024; idx += 256) {
        int hh = idx >> 5, w4 = idx & 31;
        cpa16(xsA + (hh*132 + w4*4)*4, xp + hh*128 + w4*4);
    }
    cpa_commit();

    int qr = lane >> 2, qc = lane & 3, lr = lane & 7, lg = lane >> 3;

    // ---- stage 1: 4 hq tiles, 8 warps per tile ----
    {
        int m0 = (warp & 1)*16, n0 = (warp >> 1)*8;
        // x2 B-frag: lanes 0..15 address rows n0+lr, k-offset (lg&1)*4
        unsigned bBase = EsA + ((n0 + lr)*132 + (lg & 1)*4)*4;
        #pragma unroll
        for (int hq = 0; hq < 4; hq++) {
            cpa_wait_all();
            __syncthreads();

            unsigned aBase = xsA + ((m0 + lr + (lg & 1)*8)*132 + (lg >> 1)*4)*4;

            float acc[4];
            acc[0] = acc[1] = acc[2] = acc[3] = 0.f;
            #pragma unroll
            for (int kk = 0; kk < 16; kk++) {
                unsigned a0, a1, a2, a3, b0, b1;
                ldsm4(a0, a1, a2, a3, aBase + kk*32);
                ldsm2(b0, b1, bBase + kk*32);
                mma_tf32(acc, a0, a1, a2, a3, b0, b1);
            }
            __syncthreads();     // all warps done reading xs
            if (hq < 3) {
                const float* src = xp + (hq+1)*4096;
                for (int idx = t; idx < 1024; idx += 256) {
                    int hh = idx >> 5, w4 = idx & 31;
                    cpa16(xsA + (hh*132 + w4*4)*4, src + hh*128 + w4*4);
                }
                cpa_commit();
            }
            // C[m16 h, n8] -> P[n][h]
            #pragma unroll
            for (int half = 0; half < 2; half++)
                #pragma unroll
                for (int cc = 0; cc < 2; cc++)
                    Pb[(n0 + 2*qc + cc)*132 + hq*32 + m0 + qr + half*8] =
                        tf32f(acc[half*2 + cc]);
        }
    }
    __syncthreads();

    // ---- stage 2: 8 warps, one chain each ----
    {
        int mt = warp & 1, nt = warp >> 1;   // mt: cos/-sin rows; nt: Pr/Pi x lhalf
        unsigned aB = EsA + ((mt*16 + lr + (lg & 1)*8)*132 + (lg >> 1)*4)*4;
        unsigned bB = PbA + ((nt*8 + lr)*132 + (lg & 1)*4)*4;

        float acc[4];
        acc[0] = acc[1] = acc[2] = acc[3] = 0.f;
        #pragma unroll
        for (int kk = 0; kk < 16; kk++) {
            unsigned a0, a1, a2, a3, b0, b1;
            ldsm4(a0, a1, a2, a3, aB + kk*32);
            ldsm2(b0, b1, bB + kk*32);
            mma_tf32(acc, a0, a1, a2, a3, b0, b1);
        }
        __syncthreads();   // xs no longer needed; reuse as Cs
        // Cs[(mt*4+nt)][k(16)][lm(8)]
        #pragma unroll
        for (int half = 0; half < 2; half++)
            #pragma unroll
            for (int cc = 0; cc < 2; cc++)
                Cs[((mt*4 + nt)*16 + qr + half*8)*8 + 2*qc + cc] =
                    acc[half*2 + cc];
    }
    __syncthreads();

    // combine + store: t -> (k, l)
    {
        int k = t >> 4, l = t & 15;
        int lh = l >> 3, lm = l & 7;
        float cPr = Cs[((0*4 + lh    )*16 + k)*8 + lm];
        float cPi = Cs[((0*4 + 2 + lh)*16 + k)*8 + lm];
        float sPr = Cs[((1*4 + lh    )*16 + k)*8 + lm];
        float sPi = Cs[((1*4 + 2 + lh)*16 + k)*8 + lm];
        float xr = (cPr - sPi) * (1.f/128.f);
        float xi = (cPi + sPr) * (1.f/128.f);
        d_X[((size_t)b*256 + k*16 + l)*64 + ci] = make_float2(xr, xi);
    }
}

// ---------------- per-mode channel mixing (o-split x4) -------------------
__global__ __launch_bounds__(256) void k_mix() {
    __shared__ float2 Ws[64*16];    // [i][ol]
    __shared__ float2 Xs[16*64];    // [b][i]
    int kl = blockIdx.x, oq = blockIdx.y, t = threadIdx.x;
    for (int idx = t; idx < 1024; idx += 256)
        Ws[idx] = d_Wt[kl*4096 + (idx >> 4)*64 + oq*16 + (idx & 15)];
    for (int idx = t; idx < 1024; idx += 256)
        Xs[idx] = d_X[((size_t)(idx >> 6)*256 + kl)*64 + (idx & 63)];
    __syncthreads();
    int ol = t & 15, b = t >> 4;
    float yr = 0.f, yi = 0.f;
    #pragma unroll 8
    for (int i = 0; i < 64; i++) {
        float2 xv = Xs[b*64 + i];
        float2 wv = Ws[i*16 + ol];
        yr += xv.x*wv.x - xv.y*wv.y;
        yi += xv.x*wv.y + xv.y*wv.x;
    }
    d_Y[((size_t)b*256 + kl)*64 + oq*16 + ol] = make_float2(yr, yi);
}

// ---------------- inverse stage 1 (over k) -------------------------------
__global__ __launch_bounds__(256) void k_invh() {
    __shared__ float2 Ys[256];
    __shared__ float2 twd[128];
    int t = threadIdx.x, bo = blockIdx.x;
    int b = bo >> 6, o = bo & 63;
    if (t < 128) twd[t] = d_twdp[t];
    Ys[t] = d_Y[((size_t)b*256 + t)*64 + o];
    __syncthreads();
    #pragma unroll
    for (int rep = 0; rep < 8; rep++) {
        int idx = rep*256 + t;
        int h = idx >> 4, l = idx & 15;
        float zr = 0.f, zi = 0.f;
        #pragma unroll
        for (int k = 0; k < 16; k++) {
            float2 y = Ys[k*16 + l];
            float2 e = twd[(k*h) & 127];
            zr += y.x*e.x - y.y*e.y;
            zi += y.x*e.y + y.y*e.x;
        }
        float f = (l == 0 ? 1.f : 2.f) * (1.f/128.f);
        float* zp = d_Z1 + (((size_t)b*128 + h)*64 + o)*32;
        zp[l]      = tf32f(zr*f);
        zp[16 + l] = tf32f(zi*f);
    }
}

// ---------------- fused final (w-split): C[64o,64w] = A[64,96]@B[96,64] --
#define KP 100
#define AP 100
#define OUT_SMEM ((64*KP + 64*AP + 128)*4)
__global__ __launch_bounds__(256) void k_out(const float* __restrict__ x,
                                             const float* __restrict__ bw,
                                             const float* __restrict__ bb,
                                             float* __restrict__ out) {
    extern __shared__ float sm[];
    float* Bt  = sm;               // [64 w][KP]
    float* As  = Bt + 64*KP;       // [64 o][AP]
    float* bbp = As + 64*AP;

    int t = threadIdx.x;           // 256 = 8 warps
    int b = blockIdx.x >> 7, h = blockIdx.x & 127;
    int wq = blockIdx.y;           // 0/1 -> w half

    unsigned BtA = s2u(Bt), AsA = s2u(As);

    // As cols 0..63: bw rows (raw f32, HW-truncated by mma)
    for (int idx = t; idx < 1024; idx += 256) {
        int o = idx >> 4, c4 = idx & 15;
        cpa16(AsA + (o*AP + c4*4)*4, bw + o*64 + c4*4);
    }
    // As cols 64..95: Z1 row (zr|zi, pre-rounded)
    for (int idx = t; idx < 512; idx += 256) {
        int o = idx >> 3, c4 = idx & 7;
        cpa16(AsA + (o*AP + 64 + c4*4)*4,
              d_Z1 + (((size_t)b*128 + h)*64 + o)*32 + c4*4);
    }
    // Bt cols 64..95: EoutT rows
    for (int idx = t; idx < 512; idx += 256) {
        int w = idx >> 3, c4 = idx & 7;
        cpa16(BtA + (w*KP + 64 + c4*4)*4, d_EoutT + (wq*64 + w)*32 + c4*4);
    }
    // Bt cols 0..63: x transposed (raw f32)
    for (int idx = t; idx < 1024; idx += 256) {
        int i = idx >> 4, w4 = idx & 15;
        float4 v = *(const float4*)(x + (((size_t)(b*64 + i))*128 + h)*128
                                      + wq*64 + w4*4);
        Bt[(w4*4+0)*KP + i] = v.x;
        Bt[(w4*4+1)*KP + i] = v.y;
        Bt[(w4*4+2)*KP + i] = v.z;
        Bt[(w4*4+3)*KP + i] = v.w;
    }
    if (t < 64) bbp[t] = bb[t];
    else if (t < 128) bbp[t] = d_proj[b*64 + (t - 64)];
    cpa_commit();
    cpa_wait_all();
    __syncthreads();

    int lane = t & 31, warp = t >> 5;
    int m0 = (warp & 3) * 16, n0 = (warp >> 2) * 32;
    int qr = lane >> 2, qc = lane & 3;
    int lr = lane & 7, lg = lane >> 3;

    unsigned aBase = AsA + ((m0 + lr + (lg & 1)*8)*AP + (lg >> 1)*4)*4;
    unsigned bBase = BtA + ((n0 + lr + (lg >> 1)*8)*KP + (lg & 1)*4)*4;

    float acc[4][4];
    #pragma unroll
    for (int nt = 0; nt < 4; nt++)
        #pragma unroll
        for (int j = 0; j < 4; j++) acc[nt][j] = 0.f;

    #pragma unroll
    for (int kk = 0; kk < 12; kk++) {
        unsigned a0, a1, a2, a3;
        ldsm4(a0, a1, a2, a3, aBase + kk*32);
        #pragma unroll
        for (int p = 0; p < 2; p++) {
            unsigned b0, b1, b2, b3;
            ldsm4(b0, b1, b2, b3, bBase + p*16*KP*4 + kk*32);
            mma_tf32(acc[2*p],   a0, a1, a2, a3, b0, b1);
            mma_tf32(acc[2*p+1], a0, a1, a2, a3, b2, b3);
        }
    }

    #pragma unroll
    for (int nt = 0; nt < 4; nt++) {
        #pragma unroll
        for (int half = 0; half < 2; half++) {
            int o = m0 + qr + half*8;
            float bias = bbp[o], pr = bbp[64 + o];
            float v0 = acc[nt][half*2 + 0] + bias;
            float v1 = acc[nt][half*2 + 1] + bias;
            v0 = 0.5f * v0 * (1.f + erff(v0 * 0.70710678118f)) + pr;
            v1 = 0.5f * v1 * (1.f + erff(v1 * 0.70710678118f)) + pr;
            int w = wq*64 + n0 + nt*8 + qc*2;
            *(float2*)(out + (((size_t)(b*64 + o))*128 + h)*128 + w) =
                make_float2(v0, v1);
        }
    }
}

// ---------------- launcher ----------------------------------------------
extern "C" void kernel_launch(void* const* d_in, const int* in_sizes, int n_in,
                              void* d_out, int out_size) {
    const float* x    = (const float*)d_in[0];
    const float* temb = (const float*)d_in[1];
    const float* wr   = (const float*)d_in[2];
    const float* wi   = (const float*)d_in[3];
    const float* bw   = (const float*)d_in[4];
    const float* bb   = (const float*)d_in[5];
    const float* twm  = (const float*)d_in[6];
    const float* tbv  = (const float*)d_in[7];
    float* out = (float*)d_out;

    cudaFuncSetAttribute(k_fwd, cudaFuncAttributeMaxDynamicSharedMemorySize, FWD_SMEM);
    cudaFuncSetAttribute(k_out, cudaFuncAttributeMaxDynamicSharedMemorySize, OUT_SMEM);

    k_pre <<<1153, 256>>>(temb, twm, tbv, wr, wi);
    k_fwd <<<NB*NC, 256, FWD_SMEM>>>(x);
    k_mix <<<dim3(256, 4), 256>>>();
    k_invh<<<NB*NC, 256>>>();
    k_out <<<dim3(NB*NH, 2), 256, OUT_SMEM>>>(x, bw, bb, out);
}

// round 15
// speedup vs baseline: 1.1073x; 1.0200x over previous
#include <cuda_runtime.h>
#include <math.h>

#define NB 16
#define NC 64
#define NH 128
#define NW 128
#define PI2 6.283185307179586f

// ---------------- scratch ------------------------------------------------
__device__ float2 d_X [NB*256*64];        // [b][kl][i]
__device__ float2 d_Y [NB*256*64];        // [b][kl][o]
__device__ float  d_Z1[NB*NH*64*32];      // [b][h][o][0..15 zr |16..31 zi] (tf32)
__device__ float2 d_Wt[256*64*64];        // [kl][i*64+o]
__device__ float  d_proj[NB*NC];
__device__ float  d_Eout [32*128];        // [n][w]: n<16 cos, n>=16 -sin (tf32)
__device__ float  d_EoutT[128*32];        // [w][n]  transposed copy
__device__ float2 d_twdp[128];            // e^{+i 2pi m/128}

// ---------------- helpers ------------------------------------------------
__device__ __forceinline__ unsigned tf32u(float f) {
    unsigned r; asm("cvt.rna.tf32.f32 %0, %1;" : "=r"(r) : "f"(f)); return r;
}
__device__ __forceinline__ float tf32f(float f) { return __uint_as_float(tf32u(f)); }
__device__ __forceinline__ void mma_tf32(float* c,
    unsigned a0, unsigned a1, unsigned a2, unsigned a3, unsigned b0, unsigned b1) {
    asm volatile(
        "mma.sync.aligned.m16n8k8.row.col.f32.tf32.tf32.f32 "
        "{%0,%1,%2,%3}, {%4,%5,%6,%7}, {%8,%9}, {%0,%1,%2,%3};"
        : "+f"(c[0]), "+f"(c[1]), "+f"(c[2]), "+f"(c[3])
        : "r"(a0), "r"(a1), "r"(a2), "r"(a3), "r"(b0), "r"(b1));
}
__device__ __forceinline__ unsigned s2u(const void* p) {
    unsigned a;
    asm("{ .reg .u64 t; cvta.to.shared.u64 t, %1; cvt.u32.u64 %0, t; }" : "=r"(a) : "l"(p));
    return a;
}
__device__ __forceinline__ void ldsm4(unsigned &r0, unsigned &r1, unsigned &r2,
                                      unsigned &r3, unsigned a) {
    asm volatile("ldmatrix.sync.aligned.m8n8.x4.shared.b16 {%0,%1,%2,%3}, [%4];"
        : "=r"(r0), "=r"(r1), "=r"(r2), "=r"(r3) : "r"(a));
}
__device__ __forceinline__ void ldsm2(unsigned &r0, unsigned &r1, unsigned a) {
    asm volatile("ldmatrix.sync.aligned.m8n8.x2.shared.b16 {%0,%1}, [%2];"
        : "=r"(r0), "=r"(r1) : "r"(a));
}
__device__ __forceinline__ void cpa16(unsigned dst, const void* src) {
    asm volatile("cp.async.ca.shared.global [%0], [%1], 16;" :: "r"(dst), "l"(src));
}
__device__ __forceinline__ void cpa8(unsigned dst, const void* src) {
    asm volatile("cp.async.ca.shared.global [%0], [%1], 8;" :: "r"(dst), "l"(src));
}
__device__ __forceinline__ void cpa_commit() {
    asm volatile("cp.async.commit_group;");
}
__device__ __forceinline__ void cpa_wait_all() {
    asm volatile("cp.async.wait_group 0;" ::: "memory");
}

// ---------------- merged preprocessing (prep | proj | wt) ----------------
__global__ __launch_bounds__(256) void k_pre(const float* __restrict__ temb,
                                             const float* __restrict__ twm,
                                             const float* __restrict__ tbv,
                                             const float* __restrict__ wr,
                                             const float* __restrict__ wi) {
    __shared__ float sbuf[2*32*33];
    int bid = blockIdx.x, t = threadIdx.x;

    if (bid == 0) {
        for (int idx = t; idx < 4096; idx += 256) {
            int r = idx >> 7, w = idx & 127;
            int l = r & 15;
            float s, c;
            sincosf(PI2 * (float)((l*w) & 127) * (1.f/128.f), &s, &c);
            float v = tf32f(r < 16 ? c : -s);
            d_Eout[idx] = v;
            d_EoutT[w*32 + r] = v;
        }
        if (t < 128) {
            float s, c; sincosf(PI2 * t * (1.f/128.f), &s, &c);
            d_twdp[t] = make_float2(c, s);
        }
    } else if (bid <= 128) {
        int b = (bid - 1) >> 3, cg = (bid - 1) & 7;
        float* s_silu = sbuf;
        for (int j = t; j < 512; j += 256) {
            float v = temb[b*512 + j];
            s_silu[j] = v / (1.f + __expf(-v));
        }
        __syncthreads();
        int w = t >> 5, lane = t & 31;
        int c = cg*8 + w;
        float acc = 0.f;
        #pragma unroll 4
        for (int j = lane; j < 512; j += 32) acc += s_silu[j] * twm[c*512 + j];
        #pragma unroll
        for (int off = 16; off > 0; off >>= 1)
            acc += __shfl_xor_sync(0xffffffffu, acc, off);
        if (lane == 0) d_proj[b*64 + c] = acc + tbv[c];
    } else {
        int q = bid - 129;
        int kl0 = (q & 7) * 32, io0 = (q >> 3) * 32;
        float* tr = sbuf;
        float* ti = sbuf + 32*33;
        int tx = t & 31, ty = t >> 5;
        for (int r = ty; r < 32; r += 8) {
            tr[r*33 + tx] = wr[(io0 + r)*256 + kl0 + tx];
            ti[r*33 + tx] = wi[(io0 + r)*256 + kl0 + tx];
        }
        __syncthreads();
        for (int r = ty; r < 32; r += 8) {
            d_Wt[(kl0 + r)*4096 + io0 + tx] =
                make_float2(tr[tx*33 + r], ti[tx*33 + r]);
        }
    }
}

// ---------------- fused forward DFT (one block = one bi, 8 warps) --------
#define FWD_SMEM ((32*132 + 32*132 + 32*132)*4)
__global__ __launch_bounds__(256) void k_fwd(const float* __restrict__ x) {
    extern __shared__ float sm[];
    float* Es = sm;                    // [32 n][132 w|h]
    float* xs = sm + 32*132;           // [32 h][132 w]
    float* Pb = sm + 2*32*132;         // [32 n][132 h]
    float* Cs = xs;                    // stage-2 combine buffer [8][16][8]
    int t = threadIdx.x, lane = t & 31, warp = t >> 5;
    int bi = blockIdx.x, b = bi >> 6, ci = bi & 63;

    unsigned EsA = s2u(Es), xsA = s2u(xs), PbA = s2u(Pb);
    const float* xp = x + (size_t)bi * 16384;

    for (int idx = t; idx < 1024; idx += 256) {
        int r = idx >> 5, c4 = idx & 31;
        cpa16(EsA + (r*132 + c4*4)*4, d_Eout + r*128 + c4*4);
    }
    for (int idx = t; idx < 1024; idx += 256) {
        int hh = idx >> 5, w4 = idx & 31;
        cpa16(xsA + (hh*132 + w4*4)*4, xp + hh*128 + w4*4);
    }
    cpa_commit();

    int qr = lane >> 2, qc = lane & 3, lr = lane & 7, lg = lane >> 3;

    // ---- stage 1: 4 hq tiles, 8 warps per tile ----
    {
        int m0 = (warp & 1)*16, n0 = (warp >> 1)*8;
        unsigned bBase = EsA + ((n0 + lr)*132 + (lg & 1)*4)*4;
        #pragma unroll
        for (int hq = 0; hq < 4; hq++) {
            cpa_wait_all();
            __syncthreads();

            unsigned aBase = xsA + ((m0 + lr + (lg & 1)*8)*132 + (lg >> 1)*4)*4;

            float acc[4];
            acc[0] = acc[1] = acc[2] = acc[3] = 0.f;
            #pragma unroll
            for (int kk = 0; kk < 16; kk++) {
                unsigned a0, a1, a2, a3, b0, b1;
                ldsm4(a0, a1, a2, a3, aBase + kk*32);
                ldsm2(b0, b1, bBase + kk*32);
                mma_tf32(acc, a0, a1, a2, a3, b0, b1);
            }
            __syncthreads();
            if (hq < 3) {
                const float* src = xp + (hq+1)*4096;
                for (int idx = t; idx < 1024; idx += 256) {
                    int hh = idx >> 5, w4 = idx & 31;
                    cpa16(xsA + (hh*132 + w4*4)*4, src + hh*128 + w4*4);
                }
                cpa_commit();
            }
            #pragma unroll
            for (int half = 0; half < 2; half++)
                #pragma unroll
                for (int cc = 0; cc < 2; cc++)
                    Pb[(n0 + 2*qc + cc)*132 + hq*32 + m0 + qr + half*8] =
                        tf32f(acc[half*2 + cc]);
        }
    }
    __syncthreads();

    // ---- stage 2: 8 warps, one chain each ----
    {
        int mt = warp & 1, nt = warp >> 1;
        unsigned aB = EsA + ((mt*16 + lr + (lg & 1)*8)*132 + (lg >> 1)*4)*4;
        unsigned bB = PbA + ((nt*8 + lr)*132 + (lg & 1)*4)*4;

        float acc[4];
        acc[0] = acc[1] = acc[2] = acc[3] = 0.f;
        #pragma unroll
        for (int kk = 0; kk < 16; kk++) {
            unsigned a0, a1, a2, a3, b0, b1;
            ldsm4(a0, a1, a2, a3, aB + kk*32);
            ldsm2(b0, b1, bB + kk*32);
            mma_tf32(acc, a0, a1, a2, a3, b0, b1);
        }
        __syncthreads();
        #pragma unroll
        for (int half = 0; half < 2; half++)
            #pragma unroll
            for (int cc = 0; cc < 2; cc++)
                Cs[((mt*4 + nt)*16 + qr + half*8)*8 + 2*qc + cc] =
                    acc[half*2 + cc];
    }
    __syncthreads();

    {
        int k = t >> 4, l = t & 15;
        int lh = l >> 3, lm = l & 7;
        float cPr = Cs[((0*4 + lh    )*16 + k)*8 + lm];
        float cPi = Cs[((0*4 + 2 + lh)*16 + k)*8 + lm];
        float sPr = Cs[((1*4 + lh    )*16 + k)*8 + lm];
        float sPi = Cs[((1*4 + 2 + lh)*16 + k)*8 + lm];
        float xr = (cPr - sPi) * (1.f/128.f);
        float xi = (cPi + sPr) * (1.f/128.f);
        d_X[((size_t)b*256 + k*16 + l)*64 + ci] = make_float2(xr, xi);
    }
}

// ---------------- per-mode channel mixing (o-split x4) -------------------
__global__ __launch_bounds__(256) void k_mix() {
    __shared__ float2 Ws[64*16];    // [i][ol]
    __shared__ float2 Xs[16*64];    // [b][i]
    int kl = blockIdx.x, oq = blockIdx.y, t = threadIdx.x;
    for (int idx = t; idx < 1024; idx += 256)
        Ws[idx] = d_Wt[kl*4096 + (idx >> 4)*64 + oq*16 + (idx & 15)];
    for (int idx = t; idx < 1024; idx += 256)
        Xs[idx] = d_X[((size_t)(idx >> 6)*256 + kl)*64 + (idx & 63)];
    __syncthreads();
    int ol = t & 15, b = t >> 4;
    float yr = 0.f, yi = 0.f;
    #pragma unroll 8
    for (int i = 0; i < 64; i++) {
        float2 xv = Xs[b*64 + i];
        float2 wv = Ws[i*16 + ol];
        yr += xv.x*wv.x - xv.y*wv.y;
        yi += xv.x*wv.y + xv.y*wv.x;
    }
    d_Y[((size_t)b*256 + kl)*64 + oq*16 + ol] = make_float2(yr, yi);
}

// ---------------- inverse stage 1 (tensorized) ---------------------------
// Per bo: Zr[h,l] = [C|S] @ [Yr;-Yi],  Zi[h,l] = [C|S] @ [Yi;Yr]
//   A' = [cos(2pi hk/128) | sin(...)]  (128 x 32), shared across all bo.
// Block: 4 bo; 8 warps = 8 h-tiles (m16); A-frags register-resident.
#define EAP 36
__global__ __launch_bounds__(256) void k_invh() {
    __shared__ float  Ea[128*EAP];     // [h][0..15 cos | 16..31 sin]
    __shared__ float2 Ys[4*256];       // [g][kl]
    __shared__ float  Bs[2*16*EAP];    // [mat][l][k]
    int t = threadIdx.x, lane = t & 31, warp = t >> 5;
    int bo0 = blockIdx.x * 4;
    int b = bo0 >> 6, o0 = bo0 & 63;

    // stage Y for the 4 bo
    unsigned YsA = s2u(Ys);
    for (int idx = t; idx < 1024; idx += 256) {
        int g = idx >> 8, kl = idx & 255;
        cpa8(YsA + idx*8, d_Y + (size_t)(b*256 + kl)*64 + o0 + g);
    }
    cpa_commit();

    // build A' (twiddle matrix)
    for (int idx = t; idx < 4096; idx += 256) {
        int h = idx >> 5, j = idx & 31;
        float2 e = d_twdp[(h*(j & 15)) & 127];
        Ea[h*EAP + j] = (j < 16) ? e.x : e.y;
    }
    cpa_wait_all();
    __syncthreads();

    int qr = lane >> 2, qc = lane & 3, lr = lane & 7, lg = lane >> 3;
    int m0 = warp * 16;

    // preload A-frags (bo-invariant)
    unsigned EaA = s2u(Ea) + ((m0 + lr + (lg & 1)*8)*EAP + (lg >> 1)*4)*4;
    unsigned af[4][4];
    #pragma unroll
    for (int kk = 0; kk < 4; kk++)
        ldsm4(af[kk][0], af[kk][1], af[kk][2], af[kk][3], EaA + kk*32);

    unsigned BsA = s2u(Bs);
    for (int g = 0; g < 4; g++) {
        // build B1|B2 from Y
        for (int e2 = t; e2 < 1024; e2 += 256) {
            int l = e2 & 15, k = (e2 >> 4) & 31, mat = e2 >> 9;
            float2 y = Ys[g*256 + (k & 15)*16 + l];
            float v = mat ? ((k < 16) ? y.y : y.x)
                          : ((k < 16) ? y.x : -y.y);
            Bs[mat*16*EAP + l*EAP + k] = v;
        }
        __syncthreads();

        float acc[2][2][4];
        #pragma unroll
        for (int mat = 0; mat < 2; mat++)
            #pragma unroll
            for (int nt = 0; nt < 2; nt++)
                #pragma unroll
                for (int j = 0; j < 4; j++) acc[mat][nt][j] = 0.f;

        #pragma unroll
        for (int kk = 0; kk < 4; kk++)
            #pragma unroll
            for (int mat = 0; mat < 2; mat++)
                #pragma unroll
                for (int nt = 0; nt < 2; nt++) {
                    unsigned b0, b1;
                    ldsm2(b0, b1, BsA + ((mat*16 + nt*8 + lr)*EAP + (lg & 1)*4)*4 + kk*32);
                    mma_tf32(acc[mat][nt], af[kk][0], af[kk][1], af[kk][2], af[kk][3], b0, b1);
                }

        int o = o0 + g;
        #pragma unroll
        for (int mat = 0; mat < 2; mat++)
            #pragma unroll
            for (int nt = 0; nt < 2; nt++)
                #pragma unroll
                for (int half = 0; half < 2; half++)
                    #pragma unroll
                    for (int cc = 0; cc < 2; cc++) {
                        int h = m0 + qr + half*8;
                        int l = nt*8 + 2*qc + cc;
                        float f = (l == 0 ? 1.f : 2.f) * (1.f/128.f);
                        d_Z1[(((size_t)b*128 + h)*64 + o)*32 + mat*16 + l] =
                            tf32f(acc[mat][nt][half*2 + cc] * f);
                    }
        __syncthreads();
    }
}

// ---------------- fused final (w-split): C[64o,64w] = A[64,96]@B[96,64] --
#define KP 100
#define AP 100
#define OUT_SMEM ((64*KP + 64*AP + 128)*4)
__global__ __launch_bounds__(256) void k_out(const float* __restrict__ x,
                                             const float* __restrict__ bw,
                                             const float* __restrict__ bb,
                                             float* __restrict__ out) {
    extern __shared__ float sm[];
    float* Bt  = sm;               // [64 w][KP]
    float* As  = Bt + 64*KP;       // [64 o][AP]
    float* bbp = As + 64*AP;

    int t = threadIdx.x;
    int b = blockIdx.x >> 7, h = blockIdx.x & 127;
    int wq = blockIdx.y;

    unsigned BtA = s2u(Bt), AsA = s2u(As);

    for (int idx = t; idx < 1024; idx += 256) {
        int o = idx >> 4, c4 = idx & 15;
        cpa16(AsA + (o*AP + c4*4)*4, bw + o*64 + c4*4);
    }
    for (int idx = t; idx < 512; idx += 256) {
        int o = idx >> 3, c4 = idx & 7;
        cpa16(AsA + (o*AP + 64 + c4*4)*4,
              d_Z1 + (((size_t)b*128 + h)*64 + o)*32 + c4*4);
    }
    for (int idx = t; idx < 512; idx += 256) {
        int w = idx >> 3, c4 = idx & 7;
        cpa16(BtA + (w*KP + 64 + c4*4)*4, d_EoutT + (wq*64 + w)*32 + c4*4);
    }
    for (int idx = t; idx < 1024; idx += 256) {
        int i = idx >> 4, w4 = idx & 15;
        float4 v = *(const float4*)(x + (((size_t)(b*64 + i))*128 + h)*128
                                      + wq*64 + w4*4);
        Bt[(w4*4+0)*KP + i] = v.x;
        Bt[(w4*4+1)*KP + i] = v.y;
        Bt[(w4*4+2)*KP + i] = v.z;
        Bt[(w4*4+3)*KP + i] = v.w;
    }
    if (t < 64) bbp[t] = bb[t];
    else if (t < 128) bbp[t] = d_proj[b*64 + (t - 64)];
    cpa_commit();
    cpa_wait_all();
    __syncthreads();

    int lane = t & 31, warp = t >> 5;
    int m0 = (warp & 3) * 16, n0 = (warp >> 2) * 32;
    int qr = lane >> 2, qc = lane & 3;
    int lr = lane & 7, lg = lane >> 3;

    unsigned aBase = AsA + ((m0 + lr + (lg & 1)*8)*AP + (lg >> 1)*4)*4;
    unsigned bBase = BtA + ((n0 + lr + (lg >> 1)*8)*KP + (lg & 1)*4)*4;

    float acc[4][4];
    #pragma unroll
    for (int nt = 0; nt < 4; nt++)
        #pragma unroll
        for (int j = 0; j < 4; j++) acc[nt][j] = 0.f;

    #pragma unroll
    for (int kk = 0; kk < 12; kk++) {
        unsigned a0, a1, a2, a3;
        ldsm4(a0, a1, a2, a3, aBase + kk*32);
        #pragma unroll
        for (int p = 0; p < 2; p++) {
            unsigned b0, b1, b2, b3;
            ldsm4(b0, b1, b2, b3, bBase + p*16*KP*4 + kk*32);
            mma_tf32(acc[2*p],   a0, a1, a2, a3, b0, b1);
            mma_tf32(acc[2*p+1], a0, a1, a2, a3, b2, b3);
        }
    }

    #pragma unroll
    for (int nt = 0; nt < 4; nt++) {
        #pragma unroll
        for (int half = 0; half < 2; half++) {
            int o = m0 + qr + half*8;
            float bias = bbp[o], pr = bbp[64 + o];
            float v0 = acc[nt][half*2 + 0] + bias;
            float v1 = acc[nt][half*2 + 1] + bias;
            v0 = 0.5f * v0 * (1.f + erff(v0 * 0.70710678118f)) + pr;
            v1 = 0.5f * v1 * (1.f + erff(v1 * 0.70710678118f)) + pr;
            int w = wq*64 + n0 + nt*8 + qc*2;
            *(float2*)(out + (((size_t)(b*64 + o))*128 + h)*128 + w) =
                make_float2(v0, v1);
        }
    }
}

// ---------------- launcher ----------------------------------------------
extern "C" void kernel_launch(void* const* d_in, const int* in_sizes, int n_in,
                              void* d_out, int out_size) {
    const float* x    = (const float*)d_in[0];
    const float* temb = (const float*)d_in[1];
    const float* wr   = (const float*)d_in[2];
    const float* wi   = (const float*)d_in[3];
    const float* bw   = (const float*)d_in[4];
    const float* bb   = (const float*)d_in[5];
    const float* twm  = (const float*)d_in[6];
    const float* tbv  = (const float*)d_in[7];
    float* out = (float*)d_out;

    cudaFuncSetAttribute(k_fwd, cudaFuncAttributeMaxDynamicSharedMemorySize, FWD_SMEM);
    cudaFuncSetAttribute(k_out, cudaFuncAttributeMaxDynamicSharedMemorySize, OUT_SMEM);

    k_pre <<<1153, 256>>>(temb, twm, tbv, wr, wi);
    k_fwd <<<NB*NC, 256, FWD_SMEM>>>(x);
    k_mix <<<dim3(256, 4), 256>>>();
    k_invh<<<256, 256>>>();
    k_out <<<dim3(NB*NH, 2), 256, OUT_SMEM>>>(x, bw, bb, out);
}